// round 10
// baseline (speedup 1.0000x reference)
#include <cuda_runtime.h>
#include <cuda_bf16.h>
#include <math.h>
#include <stdint.h>

// ---------------- problem constants ----------------
#define BATCH  2
#define SEQ    2048
#define EMB    1024
#define NHEAD  16
#define HDIM   64
#define M_TOT  (BATCH * SEQ)       // 4096
#define C3     (3 * EMB)           // 3072
#define KDIM   1024

// ---------------- scratch ----------------
__device__ float    g_qkv[M_TOT * C3];        // 48 MB
__device__ float    g_att[M_TOT * EMB];       // 16 MB
__device__ float    g_Wqkv_r[EMB * C3];       // 12 MB
__device__ float    g_Wproj_r[EMB * EMB];     //  4 MB
__device__ uint32_t g_qhi[M_TOT * EMB / 2];   // Q*(0.125*log2e) hi
__device__ uint32_t g_qlo[M_TOT * EMB / 2];
__device__ uint32_t g_khi[M_TOT * EMB / 2];
__device__ uint32_t g_klo[M_TOT * EMB / 2];
__device__ uint32_t g_vthi[M_TOT * EMB / 2];  // V^T per head: [b][h][d][seq]
__device__ uint32_t g_vtlo[M_TOT * EMB / 2];

// ================= helpers =================
__device__ __forceinline__ uint32_t smem_u32(const void* p) {
    uint32_t a;
    asm("{ .reg .u64 t; cvta.to.shared.u64 t, %1; cvt.u32.u64 %0, t; }" : "=r"(a) : "l"(p));
    return a;
}
__device__ __forceinline__ float tf32r(float x) {
    uint32_t r;
    asm("cvt.rna.tf32.f32 %0, %1;" : "=r"(r) : "f"(x));
    return __uint_as_float(r);
}
__device__ __forceinline__ uint32_t tf32r_u(float x) {
    uint32_t r;
    asm("cvt.rna.tf32.f32 %0, %1;" : "=r"(r) : "f"(x));
    return r;
}
__device__ __forceinline__ void cpa16(uint32_t saddr, const void* g) {
    asm volatile("cp.async.cg.shared.global [%0], [%1], 16;" :: "r"(saddr), "l"(g));
}
#define CP_COMMIT()  asm volatile("cp.async.commit_group;")
#define CP_WAIT(n)   asm volatile("cp.async.wait_group %0;" :: "n"(n))

__device__ __forceinline__ void mma_tf32(float* d, const uint32_t* a, const uint32_t* b) {
    asm volatile(
        "mma.sync.aligned.m16n8k8.row.col.f32.tf32.tf32.f32 "
        "{%0,%1,%2,%3}, {%4,%5,%6,%7}, {%8,%9}, {%0,%1,%2,%3};"
        : "+f"(d[0]), "+f"(d[1]), "+f"(d[2]), "+f"(d[3])
        : "r"(a[0]), "r"(a[1]), "r"(a[2]), "r"(a[3]), "r"(b[0]), "r"(b[1]));
}
__device__ __forceinline__ void mma_bf16(float* d, uint32_t a0, uint32_t a1,
                                         uint32_t a2, uint32_t a3,
                                         uint32_t b0, uint32_t b1) {
    asm volatile(
        "mma.sync.aligned.m16n8k16.row.col.f32.bf16.bf16.f32 "
        "{%0,%1,%2,%3}, {%4,%5,%6,%7}, {%8,%9}, {%0,%1,%2,%3};"
        : "+f"(d[0]), "+f"(d[1]), "+f"(d[2]), "+f"(d[3])
        : "r"(a0), "r"(a1), "r"(a2), "r"(a3), "r"(b0), "r"(b1));
}
__device__ __forceinline__ void ldsm_x4(uint32_t& r0, uint32_t& r1, uint32_t& r2,
                                        uint32_t& r3, uint32_t addr) {
    asm volatile("ldmatrix.sync.aligned.m8n8.x4.shared.b16 {%0,%1,%2,%3}, [%4];"
                 : "=r"(r0), "=r"(r1), "=r"(r2), "=r"(r3) : "r"(addr));
}
__device__ __forceinline__ uint32_t pack_bf16x2(float e, float o) {
    uint32_t r;
    asm("cvt.rn.bf16x2.f32 %0, %1, %2;" : "=r"(r) : "f"(o), "f"(e));
    return r;
}
__device__ __forceinline__ void split2(float e, float o, uint32_t& whi, uint32_t& wlo) {
    whi = pack_bf16x2(e, o);
    float he = __uint_as_float(whi << 16);
    float ho = __uint_as_float(whi & 0xFFFF0000u);
    wlo = pack_bf16x2(e - he, o - ho);
}

// ================= tf32 mma.sync GEMM: 4-stage cp.async pipeline =================
// C[M,N] = round(A) @ B + bias. CTA 128x256, BK=16, 8 warps (2Mx4N), warp 64x64.
#define BM 128
#define BN 256
#define BK 16
#define NIT (KDIM / BK)          // 64
#define NSTAGE 4
#define A_PAD 20
#define B_PAD 264
#define A_STAGE (BM * A_PAD)     // 2560 floats
#define B_STAGE (BK * B_PAD)     // 4224 floats
#define STG_WORDS (A_STAGE + B_STAGE)
#define GEMM_SMEM_BYTES (NSTAGE * STG_WORDS * 4)   // 108544

__global__ void __launch_bounds__(256, 1)
gemm_tf32_mma(const float* __restrict__ A, const float* __restrict__ B,
              const float* __restrict__ bias, float* __restrict__ C, int N)
{
    extern __shared__ float gsm[];

    const int tid   = threadIdx.x;
    const int wid   = tid >> 5;
    const int lane  = tid & 31;
    const int g     = lane >> 2;
    const int q     = lane & 3;
    const int warpM = wid >> 2;
    const int warpN = wid & 3;
    const int m0    = blockIdx.y * BM;
    const int n0    = blockIdx.x * BN;

    const uint32_t smBase = smem_u32(gsm);

    auto load_tiles = [&](int it, int s) {
        const int k0 = it * BK;
        const uint32_t aBase = smBase + s * (STG_WORDS * 4);
        const uint32_t bBase = aBase + A_STAGE * 4;
#pragma unroll
        for (int j = 0; j < 2; j++) {
            int c = tid + j * 256;
            int r = c >> 2, seg = c & 3;
            cpa16(aBase + (r * A_PAD + seg * 4) * 4,
                  A + (size_t)(m0 + r) * KDIM + k0 + seg * 4);
        }
#pragma unroll
        for (int j = 0; j < 4; j++) {
            int c = tid + j * 256;
            int r = c >> 6, seg = c & 63;
            cpa16(bBase + (r * B_PAD + seg * 4) * 4,
                  B + (size_t)(k0 + r) * N + n0 + seg * 4);
        }
        CP_COMMIT();
    };

    float acc[4][8][4];
#pragma unroll
    for (int i = 0; i < 4; i++)
#pragma unroll
        for (int j = 0; j < 8; j++)
#pragma unroll
            for (int v = 0; v < 4; v++) acc[i][j][v] = 0.f;

    // prologue: 3 stages in flight
    load_tiles(0, 0);
    load_tiles(1, 1);
    load_tiles(2, 2);

    const int mbase = warpM * 64;
    const int nbase = warpN * 64;

    for (int it = 0; it < NIT; it++) {
        const int s = it & 3;
        // pending groups before wait: {it .. min(NIT-1, it+2)}
        const int cnt = NIT - it;
        if (cnt >= 3)      { CP_WAIT(2); }
        else if (cnt == 2) { CP_WAIT(1); }
        else               { CP_WAIT(0); }
        __syncthreads();
        // stage (it+3)%4 was last read in compute(it-1); all warps are past
        // the barrier above, so it is safe to overwrite now.
        if (it + 3 < NIT) load_tiles(it + 3, (it + 3) & 3);

        const float* As = gsm + s * STG_WORDS;
        const float* Bs = As + A_STAGE;

#pragma unroll
        for (int kk = 0; kk < 2; kk++) {
            const int k = kk * 8;
            uint32_t af[4][4], bf[8][2];
#pragma unroll
            for (int mt = 0; mt < 4; mt++) {
                const int rb = mbase + mt * 16;
                af[mt][0] = tf32r_u(As[(rb + g)     * A_PAD + k + q]);
                af[mt][1] = tf32r_u(As[(rb + g + 8) * A_PAD + k + q]);
                af[mt][2] = tf32r_u(As[(rb + g)     * A_PAD + k + q + 4]);
                af[mt][3] = tf32r_u(As[(rb + g + 8) * A_PAD + k + q + 4]);
            }
#pragma unroll
            for (int nt = 0; nt < 8; nt++) {
                const int cb = nbase + nt * 8;
                bf[nt][0] = __float_as_uint(Bs[(k + q)     * B_PAD + cb + g]);
                bf[nt][1] = __float_as_uint(Bs[(k + q + 4) * B_PAD + cb + g]);
            }
#pragma unroll
            for (int mt = 0; mt < 4; mt++)
#pragma unroll
                for (int nt = 0; nt < 8; nt++)
                    mma_tf32(acc[mt][nt], af[mt], bf[nt]);
        }
    }

#pragma unroll
    for (int mt = 0; mt < 4; mt++) {
        const int rm = m0 + mbase + mt * 16 + g;
#pragma unroll
        for (int nt = 0; nt < 8; nt++) {
            const int cn = n0 + nbase + nt * 8 + 2 * q;
            float2 o0, o1;
            o0.x = acc[mt][nt][0] + bias[cn];
            o0.y = acc[mt][nt][1] + bias[cn + 1];
            o1.x = acc[mt][nt][2] + bias[cn];
            o1.y = acc[mt][nt][3] + bias[cn + 1];
            *(float2*)(C + (size_t)rm * N + cn)       = o0;
            *(float2*)(C + (size_t)(rm + 8) * N + cn) = o1;
        }
    }
}

// ================= rounding helper (weights) =================
__global__ void round_tf32_kernel(const float* __restrict__ in, float* __restrict__ out, int n4)
{
    int i = blockIdx.x * blockDim.x + threadIdx.x;
    if (i < n4) {
        float4 v = ((const float4*)in)[i];
        v.x = tf32r(v.x); v.y = tf32r(v.y); v.z = tf32r(v.z); v.w = tf32r(v.w);
        ((float4*)out)[i] = v;
    }
}

// ================= prepass 1: split Q (scaled by 0.125*log2e) and K =================
#define QSCALE 0.180336879091324521f   // 0.125 * log2(e)

__global__ void __launch_bounds__(256)
split_qk_kernel(const float* __restrict__ qkv,
                uint32_t* __restrict__ qhi, uint32_t* __restrict__ qlo,
                uint32_t* __restrict__ khi, uint32_t* __restrict__ klo)
{
    int i = blockIdx.x * blockDim.x + threadIdx.x;
    if (i >= M_TOT * EMB / 4) return;
    int bt = i >> 8;
    int c4 = i & 255;
    const float* p = qkv + (size_t)bt * C3 + c4 * 4;
    float4 qv = *(const float4*)p;
    float4 kv = *(const float4*)(p + EMB);
    uint32_t h0, l0, h1, l1;
    int w = bt * (EMB / 2) + c4 * 2;
    split2(qv.x * QSCALE, qv.y * QSCALE, h0, l0);
    split2(qv.z * QSCALE, qv.w * QSCALE, h1, l1);
    qhi[w] = h0; qhi[w + 1] = h1; qlo[w] = l0; qlo[w + 1] = l1;
    split2(kv.x, kv.y, h0, l0);
    split2(kv.z, kv.w, h1, l1);
    khi[w] = h0; khi[w + 1] = h1; klo[w] = l0; klo[w + 1] = l1;
}

// ================= prepass 2: transpose+split V per head =================
__global__ void __launch_bounds__(256)
transpose_v_kernel(const float* __restrict__ qkv,
                   uint32_t* __restrict__ vthi, uint32_t* __restrict__ vtlo)
{
    __shared__ float tile[64][65];
    const int s0 = blockIdx.x * 64;
    const int h  = blockIdx.y;
    const int b  = blockIdx.z;
    const int tid = threadIdx.x;

#pragma unroll
    for (int j = 0; j < 16; j++) {
        int idx = tid + j * 256;
        int r = idx >> 6, d = idx & 63;
        tile[r][d] = qkv[(size_t)(b * SEQ + s0 + r) * C3 + 2 * EMB + h * HDIM + d];
    }
    __syncthreads();

    const int wv = tid & 31;
    const int dq = tid >> 5;
#pragma unroll
    for (int j = 0; j < 8; j++) {
        int d = dq * 8 + j;
        float e = tile[2 * wv][d];
        float o = tile[2 * wv + 1][d];
        uint32_t whi, wlo;
        split2(e, o, whi, wlo);
        size_t wi = ((size_t)(b * NHEAD + h) * HDIM + d) * (SEQ / 2) + s0 / 2 + wv;
        vthi[wi] = whi;
        vtlo[wi] = wlo;
    }
}

// ================= tensor-core causal flash attention =================
// 64-row Q tiles, 128 threads (4 warps), 2 CTAs/SM. bf16x3 + ldmatrix.
#define ROWW 36
#define ROWB 144
#define Q_WORDS      (64 * ROWW)
#define ONES_WORDS   (16 * ROWW)
#define KV_ARR_WORDS (64 * ROWW)
#define KV_ARR_BYTES (KV_ARR_WORDS * 4)
#define STAGE_WORDS  (4 * KV_ARR_WORDS)
#define STAGE_BYTES  (STAGE_WORDS * 4)
#define ATT_SMEM_WORDS (2 * Q_WORDS + ONES_WORDS + 2 * STAGE_WORDS)
#define ATT_SMEM_BYTES (ATT_SMEM_WORDS * 4)       // 94464

__global__ void __launch_bounds__(128, 2)
attn_mma_kernel(const uint32_t* __restrict__ qhi, const uint32_t* __restrict__ qlo,
                const uint32_t* __restrict__ khi, const uint32_t* __restrict__ klo,
                const uint32_t* __restrict__ vthi, const uint32_t* __restrict__ vtlo,
                float* __restrict__ out)
{
    extern __shared__ uint32_t sbuf[];
    uint32_t* Qhi  = sbuf;
    uint32_t* Qlo  = Qhi + Q_WORDS;
    uint32_t* Ones = Qlo + Q_WORDS;
    uint32_t* KV   = Ones + ONES_WORDS;

    const int qt   = (SEQ / 64 - 1) - blockIdx.x;
    const int h    = blockIdx.y;
    const int b    = blockIdx.z;
    const int tid  = threadIdx.x;
    const int w    = tid >> 5;
    const int lane = tid & 31;
    const int g    = lane >> 2;
    const int q    = lane & 3;

    const uint32_t kvS = smem_u32(KV);

    const char* qhiB = (const char*)qhi;
    const char* qloB = (const char*)qlo;
    const char* khiB = (const char*)khi;
    const char* kloB = (const char*)klo;
    const char* vhiB = (const char*)vthi;
    const char* vloB = (const char*)vtlo;
    const size_t qkRow0 = ((size_t)(b * SEQ) * EMB + h * HDIM) * 2;
    const size_t vRow0  = ((size_t)(b * NHEAD + h) * HDIM) * SEQ * 2;

    for (int i = tid; i < ONES_WORDS; i += 128)
        Ones[i] = (i < 8 * ROWW) ? 0x3F803F80u : 0u;

    {
        const uint32_t qs_hi = smem_u32(Qhi);
        const uint32_t qs_lo = smem_u32(Qlo);
#pragma unroll
        for (int j = 0; j < 8; j++) {
            int idx = j * 128 + tid;
            int plane = idx >> 9;
            int rem = idx & 511;
            int row = rem >> 3, ch = rem & 7;
            uint32_t sa = (plane ? qs_lo : qs_hi) + row * ROWB + ch * 16;
            const char* gp = (plane ? qloB : qhiB) +
                             qkRow0 + (size_t)(qt * 64 + row) * (EMB * 2) + ch * 16;
            cpa16(sa, gp);
        }
    }
    auto load_kv = [&](int kt, int s) {
        const uint32_t st = kvS + s * STAGE_BYTES;
#pragma unroll
        for (int j = 0; j < 16; j++) {
            int idx = j * 128 + tid;
            int arr = idx >> 9;
            int rem = idx & 511;
            int row = rem >> 3, ch = rem & 7;
            uint32_t sa = st + arr * KV_ARR_BYTES + row * ROWB + ch * 16;
            const char* gp;
            if (arr == 0)
                gp = khiB + qkRow0 + (size_t)(kt * 64 + row) * (EMB * 2) + ch * 16;
            else if (arr == 1)
                gp = kloB + qkRow0 + (size_t)(kt * 64 + row) * (EMB * 2) + ch * 16;
            else if (arr == 2)
                gp = vhiB + vRow0 + (size_t)row * (SEQ * 2) + kt * 128 + ch * 16;
            else
                gp = vloB + vRow0 + (size_t)row * (SEQ * 2) + kt * 128 + ch * 16;
            cpa16(sa, gp);
        }
    };
    load_kv(0, 0);
    CP_COMMIT();
    __syncthreads();

    const uint32_t kvlane = ((lane & 7) + ((lane >> 4) << 3)) * ROWB
                            + ((lane >> 3) & 1) * 16;
    uint32_t on0, on1, on2, on3;
    ldsm_x4(on0, on1, on2, on3, smem_u32(Ones) + kvlane);
    (void)on2; (void)on3;

    float o[8][4], ol[4];
#pragma unroll
    for (int t = 0; t < 8; t++)
#pragma unroll
        for (int v = 0; v < 4; v++) o[t][v] = 0.f;
#pragma unroll
    for (int v = 0; v < 4; v++) ol[v] = 0.f;
    float m0 = -1e30f, m1 = -1e30f;

    const int rb   = w * 16;
    const int row0 = qt * 64 + rb + g;
    const int row1 = row0 + 8;
    const int kend = qt + 1;

    const uint32_t qlane = (rb + (lane & 7) + ((lane >> 3) & 1) * 8) * ROWB
                           + (lane >> 4) * 16;
    const uint32_t qhiA = smem_u32(Qhi) + qlane;
    const uint32_t qloA = smem_u32(Qlo) + qlane;

    for (int kt = 0; kt < kend; kt++) {
        const int s = kt & 1;
        CP_WAIT(0);
        __syncthreads();
        if (kt + 1 < kend) { load_kv(kt + 1, s ^ 1); CP_COMMIT(); }

        const uint32_t stB  = kvS + s * STAGE_BYTES;
        const uint32_t khiA = stB + kvlane;
        const uint32_t kloA = khiA + KV_ARR_BYTES;
        const uint32_t vhiA = kloA + KV_ARR_BYTES;
        const uint32_t vloA = vhiA + KV_ARR_BYTES;

        float sc[8][4];
#pragma unroll
        for (int t = 0; t < 8; t++)
#pragma unroll
            for (int v = 0; v < 4; v++) sc[t][v] = 0.f;

#pragma unroll
        for (int j = 0; j < 4; j++) {
            uint32_t qh0, qh1, qh2, qh3, ql0, ql1, ql2, ql3;
            ldsm_x4(qh0, qh1, qh2, qh3, qhiA + j * 32);
            ldsm_x4(ql0, ql1, ql2, ql3, qloA + j * 32);
#pragma unroll
            for (int tp = 0; tp < 4; tp++) {
                uint32_t k0, k1, k2, k3, e0, e1, e2, e3;
                ldsm_x4(k0, k1, k2, k3, khiA + tp * (16 * ROWB) + j * 32);
                ldsm_x4(e0, e1, e2, e3, kloA + tp * (16 * ROWB) + j * 32);
                mma_bf16(sc[2 * tp],     qh0, qh1, qh2, qh3, k0, k1);
                mma_bf16(sc[2 * tp],     qh0, qh1, qh2, qh3, e0, e1);
                mma_bf16(sc[2 * tp],     ql0, ql1, ql2, ql3, k0, k1);
                mma_bf16(sc[2 * tp + 1], qh0, qh1, qh2, qh3, k2, k3);
                mma_bf16(sc[2 * tp + 1], qh0, qh1, qh2, qh3, e2, e3);
                mma_bf16(sc[2 * tp + 1], ql0, ql1, ql2, ql3, k2, k3);
            }
        }

        if (kt == qt) {
#pragma unroll
            for (int t = 0; t < 8; t++) {
                int col = kt * 64 + 8 * t + 2 * q;
                if (col     > row0) sc[t][0] = -1e30f;
                if (col + 1 > row0) sc[t][1] = -1e30f;
                if (col     > row1) sc[t][2] = -1e30f;
                if (col + 1 > row1) sc[t][3] = -1e30f;
            }
        }

        float mx0 = -1e30f, mx1 = -1e30f;
#pragma unroll
        for (int t = 0; t < 8; t++) {
            mx0 = fmaxf(mx0, fmaxf(sc[t][0], sc[t][1]));
            mx1 = fmaxf(mx1, fmaxf(sc[t][2], sc[t][3]));
        }
        mx0 = fmaxf(mx0, __shfl_xor_sync(0xffffffffu, mx0, 1));
        mx0 = fmaxf(mx0, __shfl_xor_sync(0xffffffffu, mx0, 2));
        mx1 = fmaxf(mx1, __shfl_xor_sync(0xffffffffu, mx1, 1));
        mx1 = fmaxf(mx1, __shfl_xor_sync(0xffffffffu, mx1, 2));

        float mn0 = fmaxf(m0, mx0), mn1 = fmaxf(m1, mx1);
        float a0 = exp2f(m0 - mn0), a1 = exp2f(m1 - mn1);
        m0 = mn0; m1 = mn1;
#pragma unroll
        for (int t = 0; t < 8; t++) {
            sc[t][0] = exp2f(sc[t][0] - mn0);
            sc[t][1] = exp2f(sc[t][1] - mn0);
            sc[t][2] = exp2f(sc[t][2] - mn1);
            sc[t][3] = exp2f(sc[t][3] - mn1);
        }
#pragma unroll
        for (int t = 0; t < 8; t++) {
            o[t][0] *= a0; o[t][1] *= a0;
            o[t][2] *= a1; o[t][3] *= a1;
        }
        ol[0] *= a0; ol[1] *= a0; ol[2] *= a1; ol[3] *= a1;

#pragma unroll
        for (int j = 0; j < 4; j++) {
            uint32_t ph0 = pack_bf16x2(sc[2*j][0],   sc[2*j][1]);
            uint32_t ph1 = pack_bf16x2(sc[2*j][2],   sc[2*j][3]);
            uint32_t ph2 = pack_bf16x2(sc[2*j+1][0], sc[2*j+1][1]);
            uint32_t ph3 = pack_bf16x2(sc[2*j+1][2], sc[2*j+1][3]);
            uint32_t pl0 = pack_bf16x2(sc[2*j][0]   - __uint_as_float(ph0 << 16),
                                       sc[2*j][1]   - __uint_as_float(ph0 & 0xFFFF0000u));
            uint32_t pl1 = pack_bf16x2(sc[2*j][2]   - __uint_as_float(ph1 << 16),
                                       sc[2*j][3]   - __uint_as_float(ph1 & 0xFFFF0000u));
            uint32_t pl2 = pack_bf16x2(sc[2*j+1][0] - __uint_as_float(ph2 << 16),
                                       sc[2*j+1][1] - __uint_as_float(ph2 & 0xFFFF0000u));
            uint32_t pl3 = pack_bf16x2(sc[2*j+1][2] - __uint_as_float(ph3 << 16),
                                       sc[2*j+1][3] - __uint_as_float(ph3 & 0xFFFF0000u));
            mma_bf16(ol, ph0, ph1, ph2, ph3, on0, on1);
            mma_bf16(ol, pl0, pl1, pl2, pl3, on0, on1);
#pragma unroll
            for (int tp = 0; tp < 4; tp++) {
                uint32_t v0, v1, v2, v3, u0, u1, u2, u3;
                ldsm_x4(v0, v1, v2, v3, vhiA + tp * (16 * ROWB) + j * 32);
                ldsm_x4(u0, u1, u2, u3, vloA + tp * (16 * ROWB) + j * 32);
                mma_bf16(o[2 * tp],     ph0, ph1, ph2, ph3, v0, v1);
                mma_bf16(o[2 * tp],     ph0, ph1, ph2, ph3, u0, u1);
                mma_bf16(o[2 * tp],     pl0, pl1, pl2, pl3, v0, v1);
                mma_bf16(o[2 * tp + 1], ph0, ph1, ph2, ph3, v2, v3);
                mma_bf16(o[2 * tp + 1], ph0, ph1, ph2, ph3, u2, u3);
                mma_bf16(o[2 * tp + 1], pl0, pl1, pl2, pl3, v2, v3);
            }
        }
        __syncthreads();
    }

    const float inv0 = 1.f / ol[0], inv1 = 1.f / ol[2];
    const size_t ob0 = ((size_t)b * SEQ + row0) * EMB + h * HDIM;
#pragma unroll
    for (int t = 0; t < 8; t++) {
        const int col = 8 * t + 2 * q;
        float2 w0, w1;
        w0.x = o[t][0] * inv0; w0.y = o[t][1] * inv0;
        w1.x = o[t][2] * inv1; w1.y = o[t][3] * inv1;
        *(float2*)(out + ob0 + col)            = w0;
        *(float2*)(out + ob0 + 8 * EMB + col)  = w1;
    }
}

// ---------------- launcher ----------------
extern "C" void kernel_launch(void* const* d_in, const int* in_sizes, int n_in,
                              void* d_out, int out_size)
{
    const float* x     = (const float*)d_in[0];
    const float* Wqkv  = (const float*)d_in[1];
    const float* bqkv  = (const float*)d_in[2];
    const float* Wproj = (const float*)d_in[3];
    const float* bproj = (const float*)d_in[4];
    float* out = (float*)d_out;

    float *qkv_p, *att_p, *wq_p, *wp_p;
    uint32_t *qhi_p, *qlo_p, *khi_p, *klo_p, *vhi_p, *vlo_p;
    cudaGetSymbolAddress((void**)&qkv_p, g_qkv);
    cudaGetSymbolAddress((void**)&att_p, g_att);
    cudaGetSymbolAddress((void**)&wq_p,  g_Wqkv_r);
    cudaGetSymbolAddress((void**)&wp_p,  g_Wproj_r);
    cudaGetSymbolAddress((void**)&qhi_p, g_qhi);
    cudaGetSymbolAddress((void**)&qlo_p, g_qlo);
    cudaGetSymbolAddress((void**)&khi_p, g_khi);
    cudaGetSymbolAddress((void**)&klo_p, g_klo);
    cudaGetSymbolAddress((void**)&vhi_p, g_vthi);
    cudaGetSymbolAddress((void**)&vlo_p, g_vtlo);

    cudaFuncSetAttribute(attn_mma_kernel, cudaFuncAttributeMaxDynamicSharedMemorySize,
                         (int)ATT_SMEM_BYTES);
    cudaFuncSetAttribute(gemm_tf32_mma, cudaFuncAttributeMaxDynamicSharedMemorySize,
                         (int)GEMM_SMEM_BYTES);

    // 0) tf32-round weights
    round_tf32_kernel<<<(EMB * C3 / 4 + 255) / 256, 256>>>(Wqkv, wq_p, EMB * C3 / 4);
    round_tf32_kernel<<<(EMB * EMB / 4 + 255) / 256, 256>>>(Wproj, wp_p, EMB * EMB / 4);

    // 1) qkv = x @ W_qkv + b_qkv
    gemm_tf32_mma<<<dim3(C3 / BN, M_TOT / BM), 256, GEMM_SMEM_BYTES>>>(x, wq_p, bqkv, qkv_p, C3);

    // 2a) pre-split Q/K, transpose+split V
    split_qk_kernel<<<(M_TOT * EMB / 4 + 255) / 256, 256>>>(qkv_p, qhi_p, qlo_p, khi_p, klo_p);
    transpose_v_kernel<<<dim3(SEQ / 64, NHEAD, BATCH), 256>>>(qkv_p, vhi_p, vlo_p);

    // 2b) causal attention
    attn_mma_kernel<<<dim3(SEQ / 64, NHEAD, BATCH), 128, ATT_SMEM_BYTES>>>(
        qhi_p, qlo_p, khi_p, klo_p, vhi_p, vlo_p, att_p);

    // 3) out = att @ W_proj + b_proj
    gemm_tf32_mma<<<dim3(EMB / BN, M_TOT / BM), 256, GEMM_SMEM_BYTES>>>(att_p, wp_p, bproj, out, EMB);
}